// round 10
// baseline (speedup 1.0000x reference)
#include <cuda_runtime.h>
#include <cuda_bf16.h>

// NCEAverage: B=256, D=128, N=1e6, K1=2048, T=0.07, MOMENTUM=0.5
// Output: [ out_l(B*K1) | out_ab(B*K1) | new_memory_l(N*D) | new_memory_ab(N*D) ]
//
// R10: R9 structure, but streaming passes process 2 consecutive rows per warp
// per iteration with software-pipelined prefetch (deeper MLP, fewer loop
// overheads, 4 blocks/SM so regs aren't capped at 32). Overflow fixup is
// folded into the update kernel.

#define DIM      128
#define T_INV    (1.0f / 0.07f)
#define N_MAX    1048576
#define CAP      12

__device__ int g_count[N_MAX];
__device__ int g_tasks[N_MAX * CAP];
__device__ int g_ovf  [4096];
__device__ int g_novf;

// ---------------- build: bucket scatter ----------------
__global__ void k_scatter(const int* __restrict__ idx, int bk) {
    for (int t = blockIdx.x * blockDim.x + threadIdx.x; t < bk;
         t += gridDim.x * blockDim.x) {
        const int row  = idx[t];
        const int slot = atomicAdd(&g_count[row], 1);
        if (slot < CAP) g_tasks[row * CAP + slot] = t;
        else            g_ovf[atomicAdd(&g_novf, 1)] = t;
    }
}

// ---------------- streaming pass: copy + score, 2 rows/warp/iter ------------
__device__ __forceinline__ void score_row(
    int r, int cnt, const float4& v, const float4* __restrict__ query,
    float* __restrict__ out_score, int K1, int lane)
{
    if (cnt <= 0) return;
    if (cnt > CAP) cnt = CAP;
    const int base = r * CAP;
    for (int j = 0; j < cnt; ++j) {
        const int task = g_tasks[base + j];
        const int b    = task / K1;
        const float4 q = query[b * 32 + lane];
        float s = v.x * q.x + v.y * q.y + v.z * q.z + v.w * q.w;
        #pragma unroll
        for (int o = 16; o; o >>= 1) s += __shfl_xor_sync(0xffffffffu, s, o);
        if (lane == 0) out_score[task] = s * T_INV;
    }
}

__global__ void __launch_bounds__(256) stream_score(
    const float4* __restrict__ bank, float4* __restrict__ outb,
    const float4* __restrict__ query, float* __restrict__ out_score,
    int Nrows, int K1)
{
    const int lane   = threadIdx.x & 31;
    const int nwarps = gridDim.x * (blockDim.x >> 5);
    const int stride = nwarps * 2;
    int r = (blockIdx.x * (blockDim.x >> 5) + (threadIdx.x >> 5)) * 2;

    if (r >= Nrows) return;

    // prologue: load current pair
    float4 v0 = __ldcs(&bank[(long long)r * 32 + lane]);
    int    c0 = g_count[r];
    float4 v1;
    int    c1 = 0;
    const bool has1 = (r + 1 < Nrows);
    if (has1) { v1 = __ldcs(&bank[(long long)(r + 1) * 32 + lane]); c1 = g_count[r + 1]; }

    while (true) {
        const int rn = r + stride;
        float4 n0, n1;
        int    d0 = 0, d1 = 0;
        bool   hn0 = (rn < Nrows), hn1 = (rn + 1 < Nrows);
        if (hn0) { n0 = __ldcs(&bank[(long long)rn * 32 + lane]);       d0 = g_count[rn]; }
        if (hn1) { n1 = __ldcs(&bank[(long long)(rn + 1) * 32 + lane]); d1 = g_count[rn + 1]; }

        // unconditional copies (store depends only on streamed values)
        __stcs(&outb[(long long)r * 32 + lane], v0);
        if (has1) __stcs(&outb[(long long)(r + 1) * 32 + lane], v1);

        score_row(r, c0, v0, query, out_score, K1, lane);
        if (has1) score_row(r + 1, c1, v1, query, out_score, K1, lane);

        if (!hn0) break;
        r  = rn;
        v0 = n0; c0 = d0;
        v1 = n1; c1 = d1;
        // has1 for the new pair == hn1
        if (!hn1) { c1 = 0; }
        // emulate has1 without extra reg: recompute cheap predicate
        if (rn + 1 >= Nrows) {
            // process last lone row on next loop iteration with has1=false path
        }
    }
}

// ---------------- update (+ overflow fixup in block B) ----------------
__global__ void __launch_bounds__(DIM) update_kernel(
    const float* __restrict__ l, const float* __restrict__ ab,
    const int* __restrict__ y, const int* __restrict__ idx,
    const float* __restrict__ mem_l, const float* __restrict__ mem_ab,
    float* __restrict__ out_l, float* __restrict__ out_ab,
    float* __restrict__ out_ml, float* __restrict__ out_mab, int B, int K1)
{
    const int tid = threadIdx.x;

    if (blockIdx.x == (unsigned)B) {
        // ---- overflow tasks (expected none) ----
        const int n = g_novf;
        const int lane = tid & 31;
        for (int i = tid >> 5; i < n; i += 4) {
            const int task = g_ovf[i];
            const int b    = task / K1;
            const long long row = idx[task];
            const float4 wl  = ((const float4*)(mem_l  + row * DIM))[lane];
            const float4 wab = ((const float4*)(mem_ab + row * DIM))[lane];
            const float4 q1  = ((const float4*)ab)[b * 32 + lane];
            const float4 q2  = ((const float4*)l )[b * 32 + lane];
            float s1 = wl.x * q1.x + wl.y * q1.y + wl.z * q1.z + wl.w * q1.w;
            float s2 = wab.x * q2.x + wab.y * q2.y + wab.z * q2.z + wab.w * q2.w;
            #pragma unroll
            for (int o = 16; o; o >>= 1) {
                s1 += __shfl_xor_sync(0xffffffffu, s1, o);
                s2 += __shfl_xor_sync(0xffffffffu, s2, o);
            }
            if (lane == 0) {
                out_ab[task] = s1 * T_INV;
                out_l [task] = s2 * T_INV;
            }
        }
        return;
    }

    const int b = blockIdx.x;
    __shared__ int skip;
    __shared__ int yy_s;
    if (tid == 0) { skip = 0; yy_s = y[b]; }
    __syncthreads();
    const int yy = yy_s;
    for (int j = b + 1 + tid; j < B; j += DIM)
        if (y[j] == yy) skip = 1;     // benign race
    __syncthreads();
    if (skip) return;

    const long long r = yy;
    const float vl  = 0.5f * mem_l [r * DIM + tid] + 0.5f * l [b * DIM + tid];
    const float vab = 0.5f * mem_ab[r * DIM + tid] + 0.5f * ab[b * DIM + tid];

    float sl = vl * vl, sab = vab * vab;
    #pragma unroll
    for (int off = 16; off; off >>= 1) {
        sl  += __shfl_xor_sync(0xffffffffu, sl,  off);
        sab += __shfl_xor_sync(0xffffffffu, sab, off);
    }
    __shared__ float wsl[4], wsab[4];
    const int w = tid >> 5, lane = tid & 31;
    if (lane == 0) { wsl[w] = sl; wsab[w] = sab; }
    __syncthreads();
    const float tsl  = wsl[0]  + wsl[1]  + wsl[2]  + wsl[3];
    const float tsab = wsab[0] + wsab[1] + wsab[2] + wsab[3];

    out_ml [r * DIM + tid] = vl  * rsqrtf(tsl);
    out_mab[r * DIM + tid] = vab * rsqrtf(tsab);
}

extern "C" void kernel_launch(void* const* d_in, const int* in_sizes, int n_in,
                              void* d_out, int out_size)
{
    const float* l      = (const float*)d_in[0];
    const float* ab     = (const float*)d_in[1];
    const int*   y      = (const int*)  d_in[2];
    const int*   idx    = (const int*)  d_in[3];
    const float* mem_l  = (const float*)d_in[4];
    const float* mem_ab = (const float*)d_in[5];

    const int       B     = in_sizes[2];
    const int       BK    = in_sizes[3];
    const int       K1    = BK / B;
    const long long ND    = (long long)in_sizes[4];
    const int       Nrows = (int)(ND / DIM);

    float* out = (float*)d_out;
    float* out_l   = out;
    float* out_ab  = out + BK;
    float* out_ml  = out + 2LL * BK;
    float* out_mab = out + 2LL * BK + ND;

    // ---- reset metadata (no allocation; graph-capturable) ----
    void* p_count; cudaGetSymbolAddress(&p_count, g_count);
    void* p_novf;  cudaGetSymbolAddress(&p_novf,  g_novf);
    cudaMemsetAsync(p_count, 0, (size_t)Nrows * sizeof(int));
    cudaMemsetAsync(p_novf,  0, sizeof(int));

    // ---- build: row->task buckets ----
    k_scatter<<<512, 1024>>>(idx, BK);

    // ---- pass 1: bank_l -> out_ml, score vs ab -> out_ab ----
    stream_score<<<148 * 4, 256>>>((const float4*)mem_l, (float4*)out_ml,
                                   (const float4*)ab, out_ab, Nrows, K1);

    // ---- pass 2: bank_ab -> out_mab, score vs l -> out_l ----
    stream_score<<<148 * 4, 256>>>((const float4*)mem_ab, (float4*)out_mab,
                                   (const float4*)l, out_l, Nrows, K1);

    // ---- row updates + overflow fixup ----
    update_kernel<<<B + 1, DIM>>>(l, ab, y, idx, mem_l, mem_ab,
                                  out_l, out_ab, out_ml, out_mab, B, K1);
}